// round 15
// baseline (speedup 1.0000x reference)
#include <cuda_runtime.h>

#define LOG2E 1.4426950408889634f
#define BLK 128
#define ROWSTR 22   // floats/staged row: x0..x8 @0..8, y0..y8 @12..20 (8B-aligned rows)

typedef unsigned long long u64;

__device__ __forceinline__ float ex2f(float x){ float y; asm("ex2.approx.f32 %0, %1;" : "=f"(y) : "f"(x)); return y; }
__device__ __forceinline__ float rcpf(float x){ float y; asm("rcp.approx.f32 %0, %1;" : "=f"(y) : "f"(x)); return y; }
__device__ __forceinline__ u64 pk(float lo, float hi){ u64 r; asm("mov.b64 %0, {%1,%2};" : "=l"(r) : "f"(lo), "f"(hi)); return r; }
__device__ __forceinline__ void unpk(u64 v, float& lo, float& hi){ asm("mov.b64 {%0,%1}, %2;" : "=f"(lo), "=f"(hi) : "l"(v)); }
__device__ __forceinline__ u64 f2fma(u64 a,u64 b,u64 c){ u64 d; asm("fma.rn.f32x2 %0, %1, %2, %3;" : "=l"(d) : "l"(a),"l"(b),"l"(c)); return d; }
__device__ __forceinline__ u64 f2add(u64 a,u64 b){ u64 d; asm("add.rn.f32x2 %0, %1, %2;" : "=l"(d) : "l"(a),"l"(b)); return d; }
__device__ __forceinline__ u64 f2mul(u64 a,u64 b){ u64 d; asm("mul.rn.f32x2 %0, %1, %2;" : "=l"(d) : "l"(a),"l"(b)); return d; }

__global__ __launch_bounds__(BLK, 7)
void logic_kernel(const float* __restrict__ state,
                  const float* __restrict__ c_templates,
                  const float* __restrict__ c_gammas,
                  const float* __restrict__ a_templates,
                  const float* __restrict__ a_gammas,
                  const float* __restrict__ a_body_W,
                  const float* __restrict__ a_body_b,
                  const float* __restrict__ a_head_W,
                  const float* __restrict__ a_head_b,
                  const float* __restrict__ act_W,
                  const float* __restrict__ act_b,
                  float* __restrict__ out, int B)
{
    // Layer-1 per rule: packed dup consts {C,u0,n0,u1,n1} for the 4 element-pairs,
    // plus scalar consts (s1a/s1b) for the 9th element.
    __shared__ u64 s1d[12][5];
    // Layer-2 per rule, packed over clause pair {j=0|j=1}, Horner form
    __shared__ u64 s2[6][5];
    // Rank-2 tail
    __shared__ u64 sH[6][4];
    __shared__ u64 sAW[6][9];
    __shared__ float4 s1a[12];   // {C, u0, n0, u1}
    __shared__ float  s1b[12];   // n1
    __shared__ float s_qb[9];
    __shared__ __align__(8) float s_io[BLK * ROWSTR];  // staging; reused for output

    const int t = threadIdx.x;

    if (t < 12) {
        float t0 = c_templates[2*t], t1 = c_templates[2*t+1];
        float w0 = (1.0f - __saturatef(c_gammas[2*t]))   * LOG2E;
        float w1 = (1.0f - __saturatef(c_gammas[2*t+1])) * LOG2E;
        float C  = -(w0*t0*t0 + w1*t1*t1);
        float u0 = 2.0f*w0*t0, u1 = 2.0f*w1*t1;
        float4 a; a.x = C; a.y = u0; a.z = -w0; a.w = u1;
        s1a[t] = a;  s1b[t] = -w1;
        s1d[t][0] = pk(C, C);   s1d[t][1] = pk(u0, u0); s1d[t][2] = pk(-w0, -w0);
        s1d[t][3] = pk(u1, u1); s1d[t][4] = pk(-w1, -w1);
    }
    if (t < 6) {
        float lo[5], hi[5];
        #pragma unroll
        for (int h = 0; h < 2; h++) {
            int g = 2*t + h;
            float a0 = a_templates[2*g], a1 = a_templates[2*g+1];
            float v0 = (1.0f - __saturatef(a_gammas[2*g]))   * LOG2E;
            float v1 = (1.0f - __saturatef(a_gammas[2*g+1])) * LOG2E;
            float* d = h ? hi : lo;
            d[0] = -(v0*a0*a0 + v1*a1*a1);
            d[1] = 2.0f*v0*a0;  d[2] = -v0;
            d[3] = 2.0f*v1*a1;  d[4] = -v1;
        }
        #pragma unroll
        for (int c = 0; c < 5; c++) s2[t][c] = pk(lo[c], hi[c]);
    }
    // H[r][j][l][m] = sum_v head_W[(2r+l)][v] * body_W[((2r+j)*4+v)][m]
    if (t < 24) {
        int r = t / 4, lm = t % 4, l = lm / 2, m = lm % 2;
        float val[2];
        #pragma unroll
        for (int j = 0; j < 2; j++) {
            float s = 0.0f;
            #pragma unroll
            for (int v = 0; v < 4; v++)
                s += a_head_W[(r*2+l)*4 + v] * a_body_W[((r*2+j)*4 + v)*2 + m];
            val[j] = s;
        }
        sH[r][l*2 + m] = pk(val[0], val[1]);
    }
    if (t < 54) {
        int r = t / 9, k = t % 9;
        sAW[r][k] = pk(act_W[k*12 + 2*r], act_W[k*12 + 2*r + 1]);
    }
    if (t < 9) {
        float s = act_b[t];
        #pragma unroll
        for (int m12 = 0; m12 < 12; m12++) {
            int r = m12 / 2;
            float cb = a_head_b[m12];
            #pragma unroll
            for (int v = 0; v < 4; v++)
                cb += a_head_W[m12*4 + v] * (a_body_b[(r*2+0)*4 + v] + a_body_b[(r*2+1)*4 + v]);
            s += act_W[t*12 + m12] * cb;
        }
        s_qb[t] = s;
    }

    // ---- coalesced input staging, de-interleaved (x block @0, y block @12) ----
    const int in_base = blockIdx.x * (BLK * 18);
    const int in_lim  = B * 18;
    const bool full = (blockIdx.x + 1) * BLK <= B;
    if (full) {
        #pragma unroll
        for (int k = t; k < BLK * 18; k += BLK) {
            float v = state[in_base + k];
            int row = k / 18, e = k % 18;
            int off = (e & 1) ? 12 + (e >> 1) : (e >> 1);
            s_io[row * ROWSTR + off] = v;
        }
    } else {
        for (int k = t; k < BLK * 18; k += BLK) {
            int g = in_base + k;
            float v = (g < in_lim) ? state[g] : 0.0f;
            int row = k / 18, e = k % 18;
            int off = (e & 1) ? 12 + (e >> 1) : (e >> 1);
            s_io[row * ROWSTR + off] = v;
        }
    }
    __syncthreads();

    // ---- per-row pair loads (t*88 and +48 both 8B-divisible; base aligned 8) ----
    u64 xp[4], yp[4];
    float x8, y8;
    {
        const u64* mx = reinterpret_cast<const u64*>(&s_io[t * ROWSTR]);
        const u64* my = reinterpret_cast<const u64*>(&s_io[t * ROWSTR + 12]);
        #pragma unroll
        for (int k = 0; k < 4; k++) { xp[k] = mx[k]; yp[k] = my[k]; }
        x8 = s_io[t * ROWSTR + 8];
        y8 = s_io[t * ROWSTR + 20];
    }

    // ---- ConcreteLayer: 12 rules, element-pair packed, packed sum/wsum ----
    float cf0[12], cf1[12];
    #pragma unroll 2
    for (int r = 0; r < 12; r++) {
        const u64 Cd = s1d[r][0], U0 = s1d[r][1], N0 = s1d[r][2], U1 = s1d[r][3], N1 = s1d[r][4];
        u64 sumd = 0ull, wsumd = 0ull;
        float mnA = -3.4e38f, mnB = -3.4e38f;
        #pragma unroll
        for (int k = 0; k < 4; k++) {
            u64 tx = f2fma(N0, xp[k], U0);
            u64 m  = f2fma(tx, xp[k], Cd);
            u64 ty = f2fma(N1, yp[k], U1);
            m = f2fma(ty, yp[k], m);             // -ms*log2e for elems 2k, 2k+1
            float mlo, mhi; unpk(m, mlo, mhi);
            mnA = fmaxf(mnA, mlo);
            mnB = fmaxf(mnB, mhi);
            u64 e = pk(ex2f(mlo), ex2f(mhi));
            sumd  = f2add(sumd, e);
            wsumd = f2fma(e, yp[k], wsumd);
        }
        // 9th element, scalar consts
        const float4 a = s1a[r];
        float m9 = fmaf(fmaf(a.z, x8, a.y), x8, a.x);
        m9 = fmaf(fmaf(s1b[r], y8, a.w), y8, m9);
        float e9 = ex2f(m9);
        float slo, shi; unpk(sumd, slo, shi);
        float wlo, whi; unpk(wsumd, wlo, whi);
        float mn = fmaxf(fmaxf(mnA, mnB), m9);
        cf0[r] = ex2f(mn);                       // exp(-min ms)
        float sum  = slo + shi + e9;
        float wsum = fmaf(e9, y8, wlo + whi);
        cf1[r] = wsum * rcpf(sum);
    }

    // ---- duplicate cf into packed pairs (xp/yp now dead) ----
    u64 cf0d[12], cf1d[12];
    #pragma unroll
    for (int i = 0; i < 12; i++) { cf0d[i] = pk(cf0[i], cf0[i]); cf1d[i] = pk(cf1[i], cf1[i]); }

    // ---- AbstractionLayer: 6 rules (clause pair packed) -> wd[r] ----
    u64 wd[6];
    #pragma unroll
    for (int r = 0; r < 6; r++) {
        const u64 Cd = s2[r][0], U0 = s2[r][1], N0 = s2[r][2], U1 = s2[r][3], N1 = s2[r][4];
        u64 sumA = 0ull, sumB = 0ull, s0 = 0ull, s1v = 0ull;
        #pragma unroll
        for (int i = 0; i < 12; i++) {
            u64 t0 = f2fma(N0, cf0d[i], U0);
            u64 m  = f2fma(t0, cf0d[i], Cd);
            u64 t1 = f2fma(N1, cf1d[i], U1);
            m = f2fma(t1, cf1d[i], m);           // -ms*log2e, both clauses
            float mlo, mhi; unpk(m, mlo, mhi);
            u64 e = pk(ex2f(mlo), ex2f(mhi));
            if (i & 1) sumB = f2add(sumB, e); else sumA = f2add(sumA, e);
            s0  = f2fma(e, cf0d[i], s0);
            s1v = f2fma(e, cf1d[i], s1v);
        }
        u64 sum = f2add(sumA, sumB);
        float slo, shi; unpk(sum, slo, shi);
        u64 inv  = pk(rcpf(slo), rcpf(shi));
        u64 sel0 = f2mul(s0, inv);
        u64 sel1 = f2mul(s1v, inv);
        u64 t0 = f2mul(sH[r][0], sel0);  t0 = f2fma(sH[r][1], sel1, t0);
        u64 t1 = f2mul(sH[r][2], sel0);  t1 = f2fma(sH[r][3], sel1, t1);
        float alo, ahi, blo, bhi;
        unpk(t0, alo, ahi); unpk(t1, blo, bhi);
        wd[r] = pk(alo + ahi, blo + bhi);
    }

    // ---- epilogue: fold wd into q, stage + store ----
    __syncthreads();
    #pragma unroll
    for (int k = 0; k < 9; k++) {
        u64 acc = pk(s_qb[k], 0.0f);
        #pragma unroll
        for (int r = 0; r < 6; r++)
            acc = f2fma(sAW[r][k], wd[r], acc);
        float lo, hi; unpk(acc, lo, hi);
        s_io[t*9 + k] = lo + hi;
    }
    __syncthreads();

    const int out_base = blockIdx.x * (BLK * 9);
    if (full) {
        #pragma unroll
        for (int k = t; k < BLK * 9; k += BLK)
            out[out_base + k] = s_io[k];
    } else {
        const int out_lim = B * 9;
        for (int k = t; k < BLK * 9; k += BLK) {
            int g = out_base + k;
            if (g < out_lim) out[g] = s_io[k];
        }
    }
}

extern "C" void kernel_launch(void* const* d_in, const int* in_sizes, int n_in,
                              void* d_out, int out_size) {
    const float* state       = (const float*)d_in[0];
    const float* c_templates = (const float*)d_in[1];
    const float* c_gammas    = (const float*)d_in[2];
    const float* a_templates = (const float*)d_in[3];
    const float* a_gammas    = (const float*)d_in[4];
    const float* a_body_W    = (const float*)d_in[5];
    const float* a_body_b    = (const float*)d_in[6];
    const float* a_head_W    = (const float*)d_in[7];
    const float* a_head_b    = (const float*)d_in[8];
    const float* act_W       = (const float*)d_in[9];
    const float* act_b       = (const float*)d_in[10];
    float* out = (float*)d_out;

    const int B = in_sizes[0] / 18;
    const int grid = (B + BLK - 1) / BLK;
    logic_kernel<<<grid, BLK>>>(state, c_templates, c_gammas, a_templates,
                                a_gammas, a_body_W, a_body_b, a_head_W,
                                a_head_b, act_W, act_b, out, B);
}

// round 16
// speedup vs baseline: 1.0318x; 1.0318x over previous
#include <cuda_runtime.h>

#define LOG2E 1.4426950408889634f
#define BLK 128
#define ROWSTR 22   // floats per staged row; interleaved (x,y) pairs, 8B-aligned rows

typedef unsigned long long u64;

__device__ __forceinline__ float ex2f(float x){ float y; asm("ex2.approx.f32 %0, %1;" : "=f"(y) : "f"(x)); return y; }
__device__ __forceinline__ float rcpf(float x){ float y; asm("rcp.approx.f32 %0, %1;" : "=f"(y) : "f"(x)); return y; }
__device__ __forceinline__ u64 pk(float lo, float hi){ u64 r; asm("mov.b64 %0, {%1,%2};" : "=l"(r) : "f"(lo), "f"(hi)); return r; }
__device__ __forceinline__ void unpk(u64 v, float& lo, float& hi){ asm("mov.b64 {%0,%1}, %2;" : "=f"(lo), "=f"(hi) : "l"(v)); }
__device__ __forceinline__ u64 f2fma(u64 a,u64 b,u64 c){ u64 d; asm("fma.rn.f32x2 %0, %1, %2, %3;" : "=l"(d) : "l"(a),"l"(b),"l"(c)); return d; }
__device__ __forceinline__ u64 f2add(u64 a,u64 b){ u64 d; asm("add.rn.f32x2 %0, %1, %2;" : "=l"(d) : "l"(a),"l"(b)); return d; }
__device__ __forceinline__ u64 f2mul(u64 a,u64 b){ u64 d; asm("mul.rn.f32x2 %0, %1, %2;" : "=l"(d) : "l"(a),"l"(b)); return d; }

__global__ __launch_bounds__(BLK, 7)
void logic_kernel(const float* __restrict__ state,
                  const float* __restrict__ c_templates,
                  const float* __restrict__ c_gammas,
                  const float* __restrict__ a_templates,
                  const float* __restrict__ a_gammas,
                  const float* __restrict__ a_body_W,
                  const float* __restrict__ a_body_b,
                  const float* __restrict__ a_head_W,
                  const float* __restrict__ a_head_b,
                  const float* __restrict__ act_W,
                  const float* __restrict__ act_b,
                  float* __restrict__ out, int B)
{
    // Layer-1 per rule, Horner: m = C + x*(u0 + n0 x) + y*(u1 + n1 y)
    __shared__ float4 s1a[12];   // {C, u0, n0, u1}
    __shared__ float  s1b[12];   // n1
    // Layer-2 per rule, packed over clause pair {j=0|j=1}, Horner form
    __shared__ u64 s2[6][5];     // {C, u0, n0, u1, n1}
    // Rank-2 tail: H packed over clause
    __shared__ u64 sH[6][4];
    __shared__ u64 sAW[6][9];    // {act_W[k][2r] | act_W[k][2r+1]}
    __shared__ float s_qb[9];
    __shared__ __align__(8) float s_io[BLK * ROWSTR];  // staging; reused for output

    const int t = threadIdx.x;

    if (t < 12) {
        float t0 = c_templates[2*t], t1 = c_templates[2*t+1];
        float w0 = (1.0f - __saturatef(c_gammas[2*t]))   * LOG2E;
        float w1 = (1.0f - __saturatef(c_gammas[2*t+1])) * LOG2E;
        float4 a;
        a.x = -(w0*t0*t0 + w1*t1*t1);   // C
        a.y = 2.0f*w0*t0;               // u0
        a.z = -w0;                      // n0
        a.w = 2.0f*w1*t1;               // u1
        s1a[t] = a;
        s1b[t] = -w1;                   // n1
    }
    if (t < 6) {
        float lo[5], hi[5];
        #pragma unroll
        for (int h = 0; h < 2; h++) {
            int g = 2*t + h;
            float a0 = a_templates[2*g], a1 = a_templates[2*g+1];
            float v0 = (1.0f - __saturatef(a_gammas[2*g]))   * LOG2E;
            float v1 = (1.0f - __saturatef(a_gammas[2*g+1])) * LOG2E;
            float* d = h ? hi : lo;
            d[0] = -(v0*a0*a0 + v1*a1*a1);
            d[1] = 2.0f*v0*a0;  d[2] = -v0;
            d[3] = 2.0f*v1*a1;  d[4] = -v1;
        }
        #pragma unroll
        for (int c = 0; c < 5; c++) s2[t][c] = pk(lo[c], hi[c]);
    }
    // H[r][j][l][m] = sum_v head_W[(2r+l)][v] * body_W[((2r+j)*4+v)][m]
    if (t < 24) {
        int r = t / 4, lm = t % 4, l = lm / 2, m = lm % 2;
        float val[2];
        #pragma unroll
        for (int j = 0; j < 2; j++) {
            float s = 0.0f;
            #pragma unroll
            for (int v = 0; v < 4; v++)
                s += a_head_W[(r*2+l)*4 + v] * a_body_W[((r*2+j)*4 + v)*2 + m];
            val[j] = s;
        }
        sH[r][l*2 + m] = pk(val[0], val[1]);
    }
    if (t < 54) {
        int r = t / 9, k = t % 9;
        sAW[r][k] = pk(act_W[k*12 + 2*r], act_W[k*12 + 2*r + 1]);
    }
    if (t < 9) {
        float s = act_b[t];
        #pragma unroll
        for (int m12 = 0; m12 < 12; m12++) {
            int r = m12 / 2;
            float cb = a_head_b[m12];
            #pragma unroll
            for (int v = 0; v < 4; v++)
                cb += a_head_W[m12*4 + v] * (a_body_b[(r*2+0)*4 + v] + a_body_b[(r*2+1)*4 + v]);
            s += act_W[t*12 + m12] * cb;
        }
        s_qb[t] = s;
    }

    // ---- coalesced input staging, incremental index (128 = 7*18 + 2) ----
    const int in_base = blockIdx.x * (BLK * 18);
    const int in_lim  = B * 18;
    const bool full = (blockIdx.x + 1) * BLK <= B;
    {
        int row = t / 18;
        int col = t - row * 18;
        int idx = row * ROWSTR + col;
        if (full) {
            #pragma unroll
            for (int e = 0; e < 18; e++) {
                s_io[idx] = state[in_base + e * BLK + t];
                col += 2;
                idx += 7 * ROWSTR + 2;                   // row += 7, col += 2
                if (col >= 18) { col -= 18; idx += ROWSTR - 18; }
            }
        } else {
            #pragma unroll
            for (int e = 0; e < 18; e++) {
                int g = in_base + e * BLK + t;
                s_io[idx] = (g < in_lim) ? state[g] : 0.0f;
                col += 2;
                idx += 7 * ROWSTR + 2;
                if (col >= 18) { col -= 18; idx += ROWSTR - 18; }
            }
        }
    }
    __syncthreads();

    // ---- per-row load: 9 float2 (8B-aligned; stride 22 -> <=2-way conflict) ----
    float x[9], y[9];
    {
        const float2* my = reinterpret_cast<const float2*>(&s_io[t * ROWSTR]);
        #pragma unroll
        for (int i = 0; i < 9; i++) { float2 v = my[i]; x[i] = v.x; y[i] = v.y; }
    }

    // ---- ConcreteLayer (scalar, Horner, split max/sum/wsum chains, 2-rule ILP) ----
    float cf0[12], cf1[12];
    #pragma unroll 2
    for (int r = 0; r < 12; r++) {
        const float4 a = s1a[r];
        const float n1 = s1b[r];
        float sumA = 0.0f, sumB = 0.0f, wsumA = 0.0f, wsumB = 0.0f;
        float mnA = -3.4e38f, mnB = -3.4e38f;
        #pragma unroll
        for (int i = 0; i < 9; i++) {
            float tx = fmaf(a.z, x[i], a.y);     // u0 + n0*x
            float m  = fmaf(tx, x[i], a.x);      // C + x*(...)
            float ty = fmaf(n1, y[i], a.w);      // u1 + n1*y
            m = fmaf(ty, y[i], m);               // m = -ms*log2e
            float e = ex2f(m);
            if (i & 1) { mnB = fmaxf(mnB, m); sumB += e; wsumB = fmaf(e, y[i], wsumB); }
            else       { mnA = fmaxf(mnA, m); sumA += e; wsumA = fmaf(e, y[i], wsumA); }
        }
        cf0[r] = ex2f(fmaxf(mnA, mnB));          // exp(-min ms)
        cf1[r] = (wsumA + wsumB) * rcpf(sumA + sumB);
    }

    // ---- duplicate cf into packed pairs (x,y now dead) ----
    u64 cf0d[12], cf1d[12];
    #pragma unroll
    for (int i = 0; i < 12; i++) { cf0d[i] = pk(cf0[i], cf0[i]); cf1d[i] = pk(cf1[i], cf1[i]); }

    // ---- AbstractionLayer: 6 rules (clause pair packed) -> wd[r] ----
    u64 wd[6];
    #pragma unroll
    for (int r = 0; r < 6; r++) {
        const u64 Cd = s2[r][0], U0 = s2[r][1], N0 = s2[r][2], U1 = s2[r][3], N1 = s2[r][4];
        u64 sumA = 0ull, sumB = 0ull, s0 = 0ull, s1v = 0ull;
        #pragma unroll
        for (int i = 0; i < 12; i++) {
            u64 t0 = f2fma(N0, cf0d[i], U0);
            u64 m  = f2fma(t0, cf0d[i], Cd);
            u64 t1 = f2fma(N1, cf1d[i], U1);
            m = f2fma(t1, cf1d[i], m);           // -ms*log2e, both clauses
            float mlo, mhi; unpk(m, mlo, mhi);
            u64 e = pk(ex2f(mlo), ex2f(mhi));
            if (i & 1) sumB = f2add(sumB, e); else sumA = f2add(sumA, e);
            s0  = f2fma(e, cf0d[i], s0);
            s1v = f2fma(e, cf1d[i], s1v);
        }
        u64 sum = f2add(sumA, sumB);
        float slo, shi; unpk(sum, slo, shi);
        u64 inv  = pk(rcpf(slo), rcpf(shi));
        u64 sel0 = f2mul(s0, inv);
        u64 sel1 = f2mul(s1v, inv);
        u64 t0 = f2mul(sH[r][0], sel0);  t0 = f2fma(sH[r][1], sel1, t0);
        u64 t1 = f2mul(sH[r][2], sel0);  t1 = f2fma(sH[r][3], sel1, t1);
        float alo, ahi, blo, bhi;
        unpk(t0, alo, ahi); unpk(t1, blo, bhi);
        wd[r] = pk(alo + ahi, blo + bhi);
    }

    // ---- epilogue: fold wd into q, stage + store ----
    __syncthreads();
    #pragma unroll
    for (int k = 0; k < 9; k++) {
        u64 acc = pk(s_qb[k], 0.0f);
        #pragma unroll
        for (int r = 0; r < 6; r++)
            acc = f2fma(sAW[r][k], wd[r], acc);
        float lo, hi; unpk(acc, lo, hi);
        s_io[t*9 + k] = lo + hi;
    }
    __syncthreads();

    const int out_base = blockIdx.x * (BLK * 9);
    if (full) {
        #pragma unroll
        for (int k = t; k < BLK * 9; k += BLK)
            out[out_base + k] = s_io[k];
    } else {
        const int out_lim = B * 9;
        for (int k = t; k < BLK * 9; k += BLK) {
            int g = out_base + k;
            if (g < out_lim) out[g] = s_io[k];
        }
    }
}

extern "C" void kernel_launch(void* const* d_in, const int* in_sizes, int n_in,
                              void* d_out, int out_size) {
    const float* state       = (const float*)d_in[0];
    const float* c_templates = (const float*)d_in[1];
    const float* c_gammas    = (const float*)d_in[2];
    const float* a_templates = (const float*)d_in[3];
    const float* a_gammas    = (const float*)d_in[4];
    const float* a_body_W    = (const float*)d_in[5];
    const float* a_body_b    = (const float*)d_in[6];
    const float* a_head_W    = (const float*)d_in[7];
    const float* a_head_b    = (const float*)d_in[8];
    const float* act_W       = (const float*)d_in[9];
    const float* act_b       = (const float*)d_in[10];
    float* out = (float*)d_out;

    const int B = in_sizes[0] / 18;
    const int grid = (B + BLK - 1) / BLK;
    logic_kernel<<<grid, BLK>>>(state, c_templates, c_gammas, a_templates,
                                a_gammas, a_body_W, a_body_b, a_head_W,
                                a_head_b, act_W, act_b, out, B);
}

// round 17
// speedup vs baseline: 1.0615x; 1.0288x over previous
#include <cuda_runtime.h>

#define LOG2E 1.4426950408889634f
#define BLK 128
#define ROWSTR 22   // floats per staged row; interleaved (x,y) pairs, 8B-aligned rows

typedef unsigned long long u64;

__device__ __forceinline__ float ex2f(float x){ float y; asm("ex2.approx.f32 %0, %1;" : "=f"(y) : "f"(x)); return y; }
__device__ __forceinline__ float rcpf(float x){ float y; asm("rcp.approx.f32 %0, %1;" : "=f"(y) : "f"(x)); return y; }
__device__ __forceinline__ u64 pk(float lo, float hi){ u64 r; asm("mov.b64 %0, {%1,%2};" : "=l"(r) : "f"(lo), "f"(hi)); return r; }
__device__ __forceinline__ void unpk(u64 v, float& lo, float& hi){ asm("mov.b64 {%0,%1}, %2;" : "=f"(lo), "=f"(hi) : "l"(v)); }
__device__ __forceinline__ u64 f2fma(u64 a,u64 b,u64 c){ u64 d; asm("fma.rn.f32x2 %0, %1, %2, %3;" : "=l"(d) : "l"(a),"l"(b),"l"(c)); return d; }
__device__ __forceinline__ u64 f2add(u64 a,u64 b){ u64 d; asm("add.rn.f32x2 %0, %1, %2;" : "=l"(d) : "l"(a),"l"(b)); return d; }
__device__ __forceinline__ u64 f2mul(u64 a,u64 b){ u64 d; asm("mul.rn.f32x2 %0, %1, %2;" : "=l"(d) : "l"(a),"l"(b)); return d; }

__global__ __launch_bounds__(BLK, 7)
void logic_kernel(const float* __restrict__ state,
                  const float* __restrict__ c_templates,
                  const float* __restrict__ c_gammas,
                  const float* __restrict__ a_templates,
                  const float* __restrict__ a_gammas,
                  const float* __restrict__ a_body_W,
                  const float* __restrict__ a_body_b,
                  const float* __restrict__ a_head_W,
                  const float* __restrict__ a_head_b,
                  const float* __restrict__ act_W,
                  const float* __restrict__ act_b,
                  float* __restrict__ out, int B)
{
    // Layer-1 per rule, Horner: m = C + x*(u0 + n0 x) + y*(u1 + n1 y)
    __shared__ float4 s1a[12];   // {C, u0, n0, u1}
    __shared__ float  s1b[12];   // n1
    // Layer-2 per rule, packed over clause pair {j=0|j=1}, Horner form
    __shared__ u64 s2[6][5];     // {C, u0, n0, u1, n1}
    // Rank-2 tail: H packed over clause
    __shared__ u64 sH[6][4];
    __shared__ u64 sAW[6][9];    // {act_W[k][2r] | act_W[k][2r+1]}
    __shared__ float s_qb[9];
    __shared__ __align__(8) float s_io[BLK * ROWSTR];  // staging; reused for output

    const int t = threadIdx.x;

    if (t < 12) {
        float t0 = c_templates[2*t], t1 = c_templates[2*t+1];
        float w0 = (1.0f - __saturatef(c_gammas[2*t]))   * LOG2E;
        float w1 = (1.0f - __saturatef(c_gammas[2*t+1])) * LOG2E;
        float4 a;
        a.x = -(w0*t0*t0 + w1*t1*t1);   // C
        a.y = 2.0f*w0*t0;               // u0
        a.z = -w0;                      // n0
        a.w = 2.0f*w1*t1;               // u1
        s1a[t] = a;
        s1b[t] = -w1;                   // n1
    }
    if (t < 6) {
        float lo[5], hi[5];
        #pragma unroll
        for (int h = 0; h < 2; h++) {
            int g = 2*t + h;
            float a0 = a_templates[2*g], a1 = a_templates[2*g+1];
            float v0 = (1.0f - __saturatef(a_gammas[2*g]))   * LOG2E;
            float v1 = (1.0f - __saturatef(a_gammas[2*g+1])) * LOG2E;
            float* d = h ? hi : lo;
            d[0] = -(v0*a0*a0 + v1*a1*a1);
            d[1] = 2.0f*v0*a0;  d[2] = -v0;
            d[3] = 2.0f*v1*a1;  d[4] = -v1;
        }
        #pragma unroll
        for (int c = 0; c < 5; c++) s2[t][c] = pk(lo[c], hi[c]);
    }
    // H[r][j][l][m] = sum_v head_W[(2r+l)][v] * body_W[((2r+j)*4+v)][m]
    if (t < 24) {
        int r = t / 4, lm = t % 4, l = lm / 2, m = lm % 2;
        float val[2];
        #pragma unroll
        for (int j = 0; j < 2; j++) {
            float s = 0.0f;
            #pragma unroll
            for (int v = 0; v < 4; v++)
                s += a_head_W[(r*2+l)*4 + v] * a_body_W[((r*2+j)*4 + v)*2 + m];
            val[j] = s;
        }
        sH[r][l*2 + m] = pk(val[0], val[1]);
    }
    if (t < 54) {
        int r = t / 9, k = t % 9;
        sAW[r][k] = pk(act_W[k*12 + 2*r], act_W[k*12 + 2*r + 1]);
    }
    if (t < 9) {
        float s = act_b[t];
        #pragma unroll
        for (int m12 = 0; m12 < 12; m12++) {
            int r = m12 / 2;
            float cb = a_head_b[m12];
            #pragma unroll
            for (int v = 0; v < 4; v++)
                cb += a_head_W[m12*4 + v] * (a_body_b[(r*2+0)*4 + v] + a_body_b[(r*2+1)*4 + v]);
            s += act_W[t*12 + m12] * cb;
        }
        s_qb[t] = s;
    }

    // ---- coalesced input staging, incremental index (128 = 7*18 + 2) ----
    const int in_base = blockIdx.x * (BLK * 18);
    const int in_lim  = B * 18;
    const bool full = (blockIdx.x + 1) * BLK <= B;
    {
        int row = t / 18;
        int col = t - row * 18;
        int idx = row * ROWSTR + col;
        if (full) {
            #pragma unroll
            for (int e = 0; e < 18; e++) {
                s_io[idx] = state[in_base + e * BLK + t];
                col += 2;
                idx += 7 * ROWSTR + 2;                   // row += 7, col += 2
                if (col >= 18) { col -= 18; idx += ROWSTR - 18; }
            }
        } else {
            #pragma unroll
            for (int e = 0; e < 18; e++) {
                int g = in_base + e * BLK + t;
                s_io[idx] = (g < in_lim) ? state[g] : 0.0f;
                col += 2;
                idx += 7 * ROWSTR + 2;
                if (col >= 18) { col -= 18; idx += ROWSTR - 18; }
            }
        }
    }
    __syncthreads();

    // ---- per-row load: 9 float2 (8B-aligned; stride 22 -> <=2-way conflict) ----
    float x[9], y[9];
    {
        const float2* my = reinterpret_cast<const float2*>(&s_io[t * ROWSTR]);
        #pragma unroll
        for (int i = 0; i < 9; i++) { float2 v = my[i]; x[i] = v.x; y[i] = v.y; }
    }

    // ---- ConcreteLayer (scalar, Horner; cf0 = max e — no extra ex2) ----
    float cf0[12], cf1[12];
    #pragma unroll 2
    for (int r = 0; r < 12; r++) {
        const float4 a = s1a[r];
        const float n1 = s1b[r];
        float sumA = 0.0f, sumB = 0.0f, wsumA = 0.0f, wsumB = 0.0f;
        float emA = 0.0f, emB = 0.0f;
        #pragma unroll
        for (int i = 0; i < 9; i++) {
            float tx = fmaf(a.z, x[i], a.y);     // u0 + n0*x
            float m  = fmaf(tx, x[i], a.x);      // C + x*(...)
            float ty = fmaf(n1, y[i], a.w);      // u1 + n1*y
            m = fmaf(ty, y[i], m);               // m = -ms*log2e
            float e = ex2f(m);                   // e = exp(-ms) > 0
            if (i & 1) { emB = fmaxf(emB, e); sumB += e; wsumB = fmaf(e, y[i], wsumB); }
            else       { emA = fmaxf(emA, e); sumA += e; wsumA = fmaf(e, y[i], wsumA); }
        }
        cf0[r] = fmaxf(emA, emB);                // max e == exp(-min ms)
        cf1[r] = (wsumA + wsumB) * rcpf(sumA + sumB);
    }

    // ---- duplicate cf into packed pairs (x,y now dead) ----
    u64 cf0d[12], cf1d[12];
    #pragma unroll
    for (int i = 0; i < 12; i++) { cf0d[i] = pk(cf0[i], cf0[i]); cf1d[i] = pk(cf1[i], cf1[i]); }

    // ---- AbstractionLayer: 6 rules (clause pair packed) -> wd[r] ----
    u64 wd[6];
    #pragma unroll
    for (int r = 0; r < 6; r++) {
        const u64 Cd = s2[r][0], U0 = s2[r][1], N0 = s2[r][2], U1 = s2[r][3], N1 = s2[r][4];
        u64 sumA = 0ull, sumB = 0ull, s0 = 0ull, s1v = 0ull;
        #pragma unroll
        for (int i = 0; i < 12; i++) {
            u64 t0 = f2fma(N0, cf0d[i], U0);
            u64 m  = f2fma(t0, cf0d[i], Cd);
            u64 t1 = f2fma(N1, cf1d[i], U1);
            m = f2fma(t1, cf1d[i], m);           // -ms*log2e, both clauses
            float mlo, mhi; unpk(m, mlo, mhi);
            u64 e = pk(ex2f(mlo), ex2f(mhi));
            if (i & 1) sumB = f2add(sumB, e); else sumA = f2add(sumA, e);
            s0  = f2fma(e, cf0d[i], s0);
            s1v = f2fma(e, cf1d[i], s1v);
        }
        u64 sum = f2add(sumA, sumB);
        float slo, shi; unpk(sum, slo, shi);
        u64 inv  = pk(rcpf(slo), rcpf(shi));
        u64 sel0 = f2mul(s0, inv);
        u64 sel1 = f2mul(s1v, inv);
        // w[l] = sum_j sum_m H[r][j][l][m] * sel_m[j]  (independent halves, 2-deep)
        u64 ta = f2mul(sH[r][0], sel0);
        u64 tb = f2mul(sH[r][1], sel1);
        u64 tc = f2mul(sH[r][2], sel0);
        u64 td = f2mul(sH[r][3], sel1);
        u64 t0 = f2add(ta, tb);
        u64 t1 = f2add(tc, td);
        float alo, ahi, blo, bhi;
        unpk(t0, alo, ahi); unpk(t1, blo, bhi);
        wd[r] = pk(alo + ahi, blo + bhi);
    }

    // ---- epilogue: fold wd into q, stage + store ----
    __syncthreads();
    #pragma unroll
    for (int k = 0; k < 9; k++) {
        u64 acc = pk(s_qb[k], 0.0f);
        #pragma unroll
        for (int r = 0; r < 6; r++)
            acc = f2fma(sAW[r][k], wd[r], acc);
        float lo, hi; unpk(acc, lo, hi);
        s_io[t*9 + k] = lo + hi;
    }
    __syncthreads();

    const int out_base = blockIdx.x * (BLK * 9);
    if (full) {
        #pragma unroll
        for (int k = t; k < BLK * 9; k += BLK)
            out[out_base + k] = s_io[k];
    } else {
        const int out_lim = B * 9;
        for (int k = t; k < BLK * 9; k += BLK) {
            int g = out_base + k;
            if (g < out_lim) out[g] = s_io[k];
        }
    }
}

extern "C" void kernel_launch(void* const* d_in, const int* in_sizes, int n_in,
                              void* d_out, int out_size) {
    const float* state       = (const float*)d_in[0];
    const float* c_templates = (const float*)d_in[1];
    const float* c_gammas    = (const float*)d_in[2];
    const float* a_templates = (const float*)d_in[3];
    const float* a_gammas    = (const float*)d_in[4];
    const float* a_body_W    = (const float*)d_in[5];
    const float* a_body_b    = (const float*)d_in[6];
    const float* a_head_W    = (const float*)d_in[7];
    const float* a_head_b    = (const float*)d_in[8];
    const float* act_W       = (const float*)d_in[9];
    const float* act_b       = (const float*)d_in[10];
    float* out = (float*)d_out;

    const int B = in_sizes[0] / 18;
    const int grid = (B + BLK - 1) / BLK;
    logic_kernel<<<grid, BLK>>>(state, c_templates, c_gammas, a_templates,
                                a_gammas, a_body_W, a_body_b, a_head_W,
                                a_head_b, act_W, act_b, out, B);
}